// round 7
// baseline (speedup 1.0000x reference)
#include <cuda_runtime.h>
#include <math.h>

#define N_USERS      100000
#define N_ITEMS      50000
#define N_ENTITIES   180000
#define N_USER_NODES 150000
#define N_REL        32
#define D            64
#define DV4          16   // D/4 float4 chunks per row

// ---------------- scratch (device globals; no allocation allowed) ----------
__device__ float g_eagg[(size_t)N_ENTITIES * D];      // entity_agg sums
__device__ float g_aagg[(size_t)N_USER_NODES * D];    // attribute_agg sums
__device__ float g_iu  [(size_t)N_ITEMS * D];         // i_u_agg sums
__device__ float g_ui  [(size_t)N_USERS * D];         // u_i_agg sums
__device__ float g_cnt_e [N_ENTITIES];
__device__ float g_cnt_a [N_USER_NODES];
__device__ float g_cnt_iu[N_ITEMS];
__device__ float g_cnt_ui[N_USERS];

// ---------------- helpers ----------------------------------------------------
__device__ __forceinline__ float4 mul4(float4 a, float4 b) {
    return make_float4(a.x * b.x, a.y * b.y, a.z * b.z, a.w * b.w);
}

typedef unsigned long long u64;

__device__ __forceinline__ u64 pk2(float lo, float hi) {
    u64 r;
    asm("mov.b64 %0, {%1, %2};" : "=l"(r) : "f"(lo), "f"(hi));
    return r;
}
__device__ __forceinline__ void ffma2(u64& d, u64 a, u64 b) {
    asm("fma.rn.f32x2 %0, %1, %2, %0;" : "+l"(d) : "l"(a), "l"(b));
}
__device__ __forceinline__ float red2(u64 v) {
    float lo, hi;
    asm("mov.b64 {%0, %1}, %2;" : "=f"(lo), "=f"(hi) : "l"(v));
    return lo + hi;
}

// ---------------- zero scratch each launch ---------------------------------
__global__ void zero_all() {
    int gid = blockIdx.x * blockDim.x + threadIdx.x;
    int stride = gridDim.x * blockDim.x;
    float4 z = make_float4(0.f, 0.f, 0.f, 0.f);
#define ZLOOP(arr, n4) { float4* p = (float4*)(arr); \
    for (int i = gid; i < (n4); i += stride) p[i] = z; }
    ZLOOP(g_eagg, N_ENTITIES * DV4)
    ZLOOP(g_aagg, N_USER_NODES * DV4)
    ZLOOP(g_iu,   N_ITEMS * DV4)
    ZLOOP(g_ui,   N_USERS * DV4)
    ZLOOP(g_cnt_e,  N_ENTITIES / 4)
    ZLOOP(g_cnt_a,  N_USER_NODES / 4)
    ZLOOP(g_cnt_iu, N_ITEMS / 4)
    ZLOOP(g_cnt_ui, N_USERS / 4)
#undef ZLOOP
}

// ---------------- typed scatter: agg[head] += emb[tail] * weight[type] -----
// 16 lanes per edge-chunk; 2-way half-split unroll so every thread keeps two
// independent gather->RED chains in flight (matches scatter_mat's MLP).
__device__ __forceinline__ void scatter_body2(
    const float4* __restrict__ emb, const float4* __restrict__ sw,
    const int* __restrict__ head, const int* __restrict__ tail,
    const int* __restrict__ etype,
    float4* __restrict__ agg, float* __restrict__ cnt, int n_edges)
{
    int gid = blockIdx.x * blockDim.x + threadIdx.x;
    int c = gid & 15;
    int stride = gridDim.x * blockDim.x;
    int half = (n_edges + 1) >> 1;
    int total = half << 4;
    for (int g = gid; g < total; g += stride) {
        int e1 = g >> 4;
        int e2 = e1 + half;
        bool v2 = (e2 < n_edges);

        int h1  = __ldg(head + e1);
        int t1  = __ldg(tail + e1);
        int ty1 = __ldg(etype + e1);
        int h2 = 0, t2 = 0, ty2 = 0;
        if (v2) { h2 = __ldg(head + e2); t2 = __ldg(tail + e2); ty2 = __ldg(etype + e2); }

        float4 a1 = __ldg(emb + t1 * DV4 + c);
        float4 a2 = v2 ? __ldg(emb + t2 * DV4 + c) : make_float4(0.f,0.f,0.f,0.f);
        float4 w1 = sw[ty1 * DV4 + c];
        float4 w2 = sw[ty2 * DV4 + c];

        atomicAdd(agg + h1 * DV4 + c, mul4(a1, w1));
        if (v2) atomicAdd(agg + h2 * DV4 + c, mul4(a2, w2));
        if (c == 0) {
            atomicAdd(cnt + h1, 1.0f);
            if (v2) atomicAdd(cnt + h2, 1.0f);
        }
    }
}

__global__ void scatter_entity(const float4* __restrict__ emb,
                               const float4* __restrict__ weight,
                               const int* __restrict__ head,
                               const int* __restrict__ tail,
                               const int* __restrict__ etype, int n)
{
    __shared__ float4 sw[N_REL * DV4];
    for (int i = threadIdx.x; i < N_REL * DV4; i += blockDim.x)
        sw[i] = __ldg(weight + i);
    __syncthreads();
    scatter_body2(emb, sw, head, tail, etype, (float4*)g_eagg, g_cnt_e, n);
}

__global__ void scatter_userkg(const float4* __restrict__ emb,
                               const float4* __restrict__ weight,
                               const int* __restrict__ head,
                               const int* __restrict__ tail,
                               const int* __restrict__ etype, int n)
{
    __shared__ float4 sw[N_REL * DV4];
    for (int i = threadIdx.x; i < N_REL * DV4; i += blockDim.x)
        sw[i] = __ldg(weight + i);
    __syncthreads();
    scatter_body2(emb, sw, head, tail, etype, (float4*)g_aagg, g_cnt_a, n);
}

// ---------------- fused interaction-matrix scatters (2-way unroll = 4 chains)
// i_u_agg[mat_col] += user_emb[mat_row]   * weight[0]
// u_i_agg[mat_row] += entity_emb[mat_col] * weight[0]
__global__ void scatter_mat(const float4* __restrict__ uemb,
                            const float4* __restrict__ eemb,
                            const float4* __restrict__ weight,
                            const int* __restrict__ mrow,
                            const int* __restrict__ mcol, int n)
{
    int gid = blockIdx.x * blockDim.x + threadIdx.x;
    int c = gid & 15;
    int stride = gridDim.x * blockDim.x;
    float4 w0 = __ldg(weight + c);          // weight[0] chunk, loop-invariant
    float4* iu = (float4*)g_iu;
    float4* ui = (float4*)g_ui;
    int half = (n + 1) >> 1;
    int total = half << 4;
    for (int g = gid; g < total; g += stride) {
        int e1 = g >> 4;
        int e2 = e1 + half;
        bool v2 = (e2 < n);

        int r1 = __ldg(mrow + e1);
        int c1 = __ldg(mcol + e1);
        int r2 = 0, c2 = 0;
        if (v2) { r2 = __ldg(mrow + e2); c2 = __ldg(mcol + e2); }

        float4 uv1 = __ldg(uemb + r1 * DV4 + c);
        float4 ev1 = __ldg(eemb + c1 * DV4 + c);
        float4 uv2 = v2 ? __ldg(uemb + r2 * DV4 + c) : make_float4(0.f,0.f,0.f,0.f);
        float4 ev2 = v2 ? __ldg(eemb + c2 * DV4 + c) : make_float4(0.f,0.f,0.f,0.f);

        atomicAdd(iu + c1 * DV4 + c, mul4(uv1, w0));
        atomicAdd(ui + r1 * DV4 + c, mul4(ev1, w0));
        if (v2) {
            atomicAdd(iu + c2 * DV4 + c, mul4(uv2, w0));
            atomicAdd(ui + r2 * DV4 + c, mul4(ev2, w0));
        }
        if (c == 0) {
            atomicAdd(g_cnt_iu + c1, 1.0f);
            atomicAdd(g_cnt_ui + r1, 1.0f);
            if (v2) {
                atomicAdd(g_cnt_iu + c2, 1.0f);
                atomicAdd(g_cnt_ui + r2, 1.0f);
            }
        }
    }
}

// ---------------- gated fusion: sigmoid(A@GA^T + B@GB^T) blend --------------
// MODE 0 (items): A = entity_agg[:N_ITEMS]/cnt, B = i_u_agg/cnt,
//                 GA = gate1, GB = gate2, out = g*A + (1-g)*B
// MODE 1 (users): A = u_i_agg/cnt, B = attr_agg[:N_USERS]/cnt,
//                 GA = gate2, GB = gate3, out = g*B + (1-g)*A
// One K=128 GEMM:  Z = [A|B] @ [GA^T ; GB^T], 64-row tile, 256 threads,
// 4x4 register tiles. Inner product uses packed fma.rn.f32x2 over K pairs:
// per 2 k-steps: 16 FFMA2 (fma pipe) + 8 packs (alu pipe) instead of 32 FFMA.
#define GPAD 68
#define GATE_SMEM ((2 * 128 * GPAD + 128) * 4)

template <int MODE>
__global__ void gate_fuse(const float* __restrict__ GA,
                          const float* __restrict__ GB,
                          float* __restrict__ out, int nrows)
{
    const float* aggA = (MODE == 0) ? g_eagg   : g_ui;
    const float* cntA = (MODE == 0) ? g_cnt_e  : g_cnt_ui;
    const float* aggB = (MODE == 0) ? g_iu     : g_aagg;
    const float* cntB = (MODE == 0) ? g_cnt_iu : g_cnt_a;

    extern __shared__ float sm[];
    float* As   = sm;                    // [128][GPAD]  (A|B transposed, normalized)
    float* Gs   = sm + 128 * GPAD;       // [128][GPAD]  (GA^T ; GB^T)
    float* invA = Gs + 128 * GPAD;       // [64]
    float* invB = invA + 64;             // [64]

    int tid = threadIdx.x;
    int row0 = blockIdx.x * 64;

    if (tid < 64) {
        int r = row0 + tid;
        invA[tid] = (r < nrows) ? 1.f / fmaxf(__ldg(cntA + r), 1.f) : 0.f;
    } else if (tid < 128) {
        int r = row0 + tid - 64;
        invB[tid - 64] = (r < nrows) ? 1.f / fmaxf(__ldg(cntB + r), 1.f) : 0.f;
    }
    __syncthreads();

    for (int idx = tid; idx < 64 * 64; idx += 256) {
        int r = idx >> 6, k = idx & 63;
        int row = row0 + r;
        float a = 0.f, b = 0.f;
        if (row < nrows) {
            a = aggA[(size_t)row * D + k] * invA[r];
            b = aggB[(size_t)row * D + k] * invB[r];
        }
        As[k * GPAD + r]        = a;
        As[(k + 64) * GPAD + r] = b;
    }
    for (int idx = tid; idx < 64 * 64; idx += 256) {
        int j = idx >> 6, k = idx & 63;          // GA[j*64+k] read coalesced
        Gs[k * GPAD + j]        = __ldg(GA + idx);
        Gs[(k + 64) * GPAD + j] = __ldg(GB + idx);
    }
    __syncthreads();

    int tx = tid & 15, ty = tid >> 4;
    u64 acc2[4][4];
#pragma unroll
    for (int i = 0; i < 4; i++)
#pragma unroll
        for (int j = 0; j < 4; j++) acc2[i][j] = 0ULL;

    const float4* As4 = (const float4*)As;
    const float4* Gs4 = (const float4*)Gs;
#pragma unroll 4
    for (int k = 0; k < 128; k += 2) {
        float4 a0 = As4[k * (GPAD / 4) + ty];
        float4 a1 = As4[(k + 1) * (GPAD / 4) + ty];
        float4 g0 = Gs4[k * (GPAD / 4) + tx];
        float4 g1 = Gs4[(k + 1) * (GPAD / 4) + tx];
        u64 aa[4] = { pk2(a0.x, a1.x), pk2(a0.y, a1.y),
                      pk2(a0.z, a1.z), pk2(a0.w, a1.w) };
        u64 gg[4] = { pk2(g0.x, g1.x), pk2(g0.y, g1.y),
                      pk2(g0.z, g1.z), pk2(g0.w, g1.w) };
#pragma unroll
        for (int i = 0; i < 4; i++)
#pragma unroll
            for (int j = 0; j < 4; j++)
                ffma2(acc2[i][j], aa[i], gg[j]);
    }

#pragma unroll
    for (int i = 0; i < 4; i++) {
        int r = ty * 4 + i;
        int row = row0 + r;
        if (row >= nrows) continue;
        float4 o;
        float* op = &o.x;
#pragma unroll
        for (int j = 0; j < 4; j++) {
            int col = tx * 4 + j;
            float z = red2(acc2[i][j]);
            float gate = 1.f / (1.f + __expf(-z));
            float a = As[col * GPAD + r];
            float b = As[(col + 64) * GPAD + r];
            op[j] = (MODE == 1) ? (gate * b + (1.f - gate) * a)
                                : (gate * a + (1.f - gate) * b);
        }
        *(float4*)(out + (size_t)row * D + tx * 4) = o;
    }
}

// ---------------- tail rows: out = agg / max(cnt, 1) ------------------------
template <int MODE>
__global__ void normalize_rows(float* __restrict__ out, int row0, int row_end)
{
    const float* agg = (MODE == 0) ? g_eagg  : g_aagg;
    const float* cnt = (MODE == 0) ? g_cnt_e : g_cnt_a;
    int gid = blockIdx.x * blockDim.x + threadIdx.x;
    int n = (row_end - row0) * DV4;
    if (gid >= n) return;
    int r = row0 + (gid >> 4);
    int c = gid & 15;
    float ic = 1.f / fmaxf(__ldg(cnt + r), 1.f);
    float4 v = ((const float4*)agg)[(size_t)r * DV4 + c];
    ((float4*)out)[(size_t)r * DV4 + c] =
        make_float4(v.x * ic, v.y * ic, v.z * ic, v.w * ic);
}

// ---------------- launch -----------------------------------------------------
extern "C" void kernel_launch(void* const* d_in, const int* in_sizes, int n_in,
                              void* d_out, int out_size)
{
    const float* entity_emb = (const float*)d_in[0];
    const float* user_emb   = (const float*)d_in[1];
    const float* weight     = (const float*)d_in[2];
    const float* gate1_w    = (const float*)d_in[3];
    const float* gate2_w    = (const float*)d_in[4];
    const float* gate3_w    = (const float*)d_in[5];
    const int*   edge_index = (const int*)d_in[6];
    const int*   edge_type  = (const int*)d_in[7];
    const int*   uedge_index= (const int*)d_in[8];
    const int*   uedge_type = (const int*)d_in[9];
    const int*   mat_row    = (const int*)d_in[10];
    const int*   mat_col    = (const int*)d_in[11];

    int n_e  = in_sizes[7];    // 1,500,000
    int n_ue = in_sizes[9];    // 1,000,000
    int n_m  = in_sizes[10];   // 1,500,000

    float* out = (float*)d_out;
    float* user_out = out + (size_t)N_ENTITIES * D;

    // opt-in >48KB dynamic smem (idempotent, capture-safe: no stream work)
    cudaFuncSetAttribute(gate_fuse<0>, cudaFuncAttributeMaxDynamicSharedMemorySize, GATE_SMEM);
    cudaFuncSetAttribute(gate_fuse<1>, cudaFuncAttributeMaxDynamicSharedMemorySize, GATE_SMEM);

    zero_all<<<2048, 256>>>();

    const int SG = 4736;   // 32 blocks/SM worth of grid-stride scatter blocks
    scatter_entity<<<SG, 256>>>((const float4*)entity_emb, (const float4*)weight,
                                edge_index, edge_index + n_e, edge_type, n_e);
    scatter_userkg<<<SG, 256>>>((const float4*)user_emb, (const float4*)weight,
                                uedge_index, uedge_index + n_ue, uedge_type, n_ue);
    scatter_mat<<<SG, 256>>>((const float4*)user_emb, (const float4*)entity_emb,
                             (const float4*)weight, mat_row, mat_col, n_m);

    gate_fuse<0><<<(N_ITEMS + 63) / 64, 256, GATE_SMEM>>>(gate1_w, gate2_w, out, N_ITEMS);
    gate_fuse<1><<<(N_USERS + 63) / 64, 256, GATE_SMEM>>>(gate2_w, gate3_w, user_out, N_USERS);

    {
        int n = (N_ENTITIES - N_ITEMS) * DV4;
        normalize_rows<0><<<(n + 255) / 256, 256>>>(out, N_ITEMS, N_ENTITIES);
    }
    {
        int n = (N_USER_NODES - N_USERS) * DV4;
        normalize_rows<1><<<(n + 255) / 256, 256>>>(user_out, N_USERS, N_USER_NODES);
    }
}

// round 8
// speedup vs baseline: 1.0064x; 1.0064x over previous
#include <cuda_runtime.h>
#include <math.h>

#define N_USERS      100000
#define N_ITEMS      50000
#define N_ENTITIES   180000
#define N_USER_NODES 150000
#define N_REL        32
#define D            64
#define DV4          16   // D/4 float4 chunks per row

// ---------------- scratch (device globals; no allocation allowed) ----------
__device__ float g_eagg[(size_t)N_ENTITIES * D];      // entity_agg sums
__device__ float g_aagg[(size_t)N_USER_NODES * D];    // attribute_agg sums
__device__ float g_iu  [(size_t)N_ITEMS * D];         // i_u_agg sums
__device__ float g_ui  [(size_t)N_USERS * D];         // u_i_agg sums
__device__ float g_cnt_e [N_ENTITIES];
__device__ float g_cnt_a [N_USER_NODES];
__device__ float g_cnt_iu[N_ITEMS];
__device__ float g_cnt_ui[N_USERS];

// ---------------- helpers ----------------------------------------------------
__device__ __forceinline__ float4 mul4(float4 a, float4 b) {
    return make_float4(a.x * b.x, a.y * b.y, a.z * b.z, a.w * b.w);
}

typedef unsigned long long u64;

__device__ __forceinline__ u64 pk2(float lo, float hi) {
    u64 r;
    asm("mov.b64 %0, {%1, %2};" : "=l"(r) : "f"(lo), "f"(hi));
    return r;
}
__device__ __forceinline__ void ffma2(u64& d, u64 a, u64 b) {
    asm("fma.rn.f32x2 %0, %1, %2, %0;" : "+l"(d) : "l"(a), "l"(b));
}
__device__ __forceinline__ float red2(u64 v) {
    float lo, hi;
    asm("mov.b64 {%0, %1}, %2;" : "=f"(lo), "=f"(hi) : "l"(v));
    return lo + hi;
}

// ---------------- zero scratch each launch ---------------------------------
__global__ void zero_all() {
    int gid = blockIdx.x * blockDim.x + threadIdx.x;
    int stride = gridDim.x * blockDim.x;
    float4 z = make_float4(0.f, 0.f, 0.f, 0.f);
#define ZLOOP(arr, n4) { float4* p = (float4*)(arr); \
    for (int i = gid; i < (n4); i += stride) p[i] = z; }
    ZLOOP(g_eagg, N_ENTITIES * DV4)
    ZLOOP(g_aagg, N_USER_NODES * DV4)
    ZLOOP(g_iu,   N_ITEMS * DV4)
    ZLOOP(g_ui,   N_USERS * DV4)
    ZLOOP(g_cnt_e,  N_ENTITIES / 4)
    ZLOOP(g_cnt_a,  N_USER_NODES / 4)
    ZLOOP(g_cnt_iu, N_ITEMS / 4)
    ZLOOP(g_cnt_ui, N_USERS / 4)
#undef ZLOOP
}

// ---------------- typed scatter: agg[head] += emb[tail] * weight[type] -----
// 16 lanes per edge (one float4 chunk each). Index loads for iteration i+1
// are issued BEFORE the gather of iteration i, so the exposed latency per
// iteration is one memory hop (gather), not two (idx -> gather).
__device__ __forceinline__ void scatter_body_pf(
    const float4* __restrict__ emb, const float4* __restrict__ sw,
    const int* __restrict__ head, const int* __restrict__ tail,
    const int* __restrict__ etype,
    float4* __restrict__ agg, float* __restrict__ cnt, int n_edges)
{
    int gid = blockIdx.x * blockDim.x + threadIdx.x;
    int c = gid & 15;
    int stride = gridDim.x * blockDim.x;
    int total = n_edges << 4;

    int g = gid;
    if (g >= total) return;
    int e = g >> 4;
    int h  = __ldg(head + e);
    int t  = __ldg(tail + e);
    int ty = __ldg(etype + e);

    while (true) {
        int gn = g + stride;
        bool more = gn < total;
        int hn = 0, tn = 0, tyn = 0;
        if (more) {                       // prefetch next indices
            int en = gn >> 4;
            hn  = __ldg(head + en);
            tn  = __ldg(tail + en);
            tyn = __ldg(etype + en);
        }
        float4 v = __ldg(emb + t * DV4 + c);
        float4 w = sw[ty * DV4 + c];
        atomicAdd(agg + h * DV4 + c, mul4(v, w));
        if (c == 0) atomicAdd(cnt + h, 1.0f);
        if (!more) break;
        g = gn; h = hn; t = tn; ty = tyn;
    }
}

__global__ void __launch_bounds__(256, 8)
scatter_entity(const float4* __restrict__ emb,
               const float4* __restrict__ weight,
               const int* __restrict__ head,
               const int* __restrict__ tail,
               const int* __restrict__ etype, int n)
{
    __shared__ float4 sw[N_REL * DV4];
    for (int i = threadIdx.x; i < N_REL * DV4; i += blockDim.x)
        sw[i] = __ldg(weight + i);
    __syncthreads();
    scatter_body_pf(emb, sw, head, tail, etype, (float4*)g_eagg, g_cnt_e, n);
}

__global__ void __launch_bounds__(256, 8)
scatter_userkg(const float4* __restrict__ emb,
               const float4* __restrict__ weight,
               const int* __restrict__ head,
               const int* __restrict__ tail,
               const int* __restrict__ etype, int n)
{
    __shared__ float4 sw[N_REL * DV4];
    for (int i = threadIdx.x; i < N_REL * DV4; i += blockDim.x)
        sw[i] = __ldg(weight + i);
    __syncthreads();
    scatter_body_pf(emb, sw, head, tail, etype, (float4*)g_aagg, g_cnt_a, n);
}

// ---------------- fused interaction-matrix scatters -------------------------
// i_u_agg[mat_col] += user_emb[mat_row]   * weight[0]
// u_i_agg[mat_row] += entity_emb[mat_col] * weight[0]
// Same index-prefetch pipeline; two independent gather->RED chains per iter.
__global__ void __launch_bounds__(256, 8)
scatter_mat(const float4* __restrict__ uemb,
            const float4* __restrict__ eemb,
            const float4* __restrict__ weight,
            const int* __restrict__ mrow,
            const int* __restrict__ mcol, int n)
{
    int gid = blockIdx.x * blockDim.x + threadIdx.x;
    int c = gid & 15;
    int stride = gridDim.x * blockDim.x;
    float4 w0 = __ldg(weight + c);          // weight[0] chunk, loop-invariant
    float4* iu = (float4*)g_iu;
    float4* ui = (float4*)g_ui;
    int total = n << 4;

    int g = gid;
    if (g >= total) return;
    int e = g >> 4;
    int r  = __ldg(mrow + e);
    int cl = __ldg(mcol + e);

    while (true) {
        int gn = g + stride;
        bool more = gn < total;
        int rn = 0, cln = 0;
        if (more) {                       // prefetch next indices
            int en = gn >> 4;
            rn  = __ldg(mrow + en);
            cln = __ldg(mcol + en);
        }
        float4 uv = __ldg(uemb + r  * DV4 + c);
        float4 ev = __ldg(eemb + cl * DV4 + c);
        atomicAdd(iu + cl * DV4 + c, mul4(uv, w0));
        atomicAdd(ui + r  * DV4 + c, mul4(ev, w0));
        if (c == 0) {
            atomicAdd(g_cnt_iu + cl, 1.0f);
            atomicAdd(g_cnt_ui + r,  1.0f);
        }
        if (!more) break;
        g = gn; r = rn; cl = cln;
    }
}

// ---------------- gated fusion: sigmoid(A@GA^T + B@GB^T) blend --------------
// MODE 0 (items): A = entity_agg[:N_ITEMS]/cnt, B = i_u_agg/cnt,
//                 GA = gate1, GB = gate2, out = g*A + (1-g)*B
// MODE 1 (users): A = u_i_agg/cnt, B = attr_agg[:N_USERS]/cnt,
//                 GA = gate2, GB = gate3, out = g*B + (1-g)*A
// One K=128 GEMM:  Z = [A|B] @ [GA^T ; GB^T], 64-row tile, 256 threads,
// 4x4 register tiles; packed fma.rn.f32x2 over K pairs (16 FFMA2 + 8 packs
// per 2 k-steps instead of 32 FFMA).
#define GPAD 68
#define GATE_SMEM ((2 * 128 * GPAD + 128) * 4)

template <int MODE>
__global__ void gate_fuse(const float* __restrict__ GA,
                          const float* __restrict__ GB,
                          float* __restrict__ out, int nrows)
{
    const float* aggA = (MODE == 0) ? g_eagg   : g_ui;
    const float* cntA = (MODE == 0) ? g_cnt_e  : g_cnt_ui;
    const float* aggB = (MODE == 0) ? g_iu     : g_aagg;
    const float* cntB = (MODE == 0) ? g_cnt_iu : g_cnt_a;

    extern __shared__ float sm[];
    float* As   = sm;                    // [128][GPAD]  (A|B transposed, normalized)
    float* Gs   = sm + 128 * GPAD;       // [128][GPAD]  (GA^T ; GB^T)
    float* invA = Gs + 128 * GPAD;       // [64]
    float* invB = invA + 64;             // [64]

    int tid = threadIdx.x;
    int row0 = blockIdx.x * 64;

    if (tid < 64) {
        int r = row0 + tid;
        invA[tid] = (r < nrows) ? 1.f / fmaxf(__ldg(cntA + r), 1.f) : 0.f;
    } else if (tid < 128) {
        int r = row0 + tid - 64;
        invB[tid - 64] = (r < nrows) ? 1.f / fmaxf(__ldg(cntB + r), 1.f) : 0.f;
    }
    __syncthreads();

    for (int idx = tid; idx < 64 * 64; idx += 256) {
        int r = idx >> 6, k = idx & 63;
        int row = row0 + r;
        float a = 0.f, b = 0.f;
        if (row < nrows) {
            a = aggA[(size_t)row * D + k] * invA[r];
            b = aggB[(size_t)row * D + k] * invB[r];
        }
        As[k * GPAD + r]        = a;
        As[(k + 64) * GPAD + r] = b;
    }
    for (int idx = tid; idx < 64 * 64; idx += 256) {
        int j = idx >> 6, k = idx & 63;          // GA[j*64+k] read coalesced
        Gs[k * GPAD + j]        = __ldg(GA + idx);
        Gs[(k + 64) * GPAD + j] = __ldg(GB + idx);
    }
    __syncthreads();

    int tx = tid & 15, ty = tid >> 4;
    u64 acc2[4][4];
#pragma unroll
    for (int i = 0; i < 4; i++)
#pragma unroll
        for (int j = 0; j < 4; j++) acc2[i][j] = 0ULL;

    const float4* As4 = (const float4*)As;
    const float4* Gs4 = (const float4*)Gs;
#pragma unroll 4
    for (int k = 0; k < 128; k += 2) {
        float4 a0 = As4[k * (GPAD / 4) + ty];
        float4 a1 = As4[(k + 1) * (GPAD / 4) + ty];
        float4 g0 = Gs4[k * (GPAD / 4) + tx];
        float4 g1 = Gs4[(k + 1) * (GPAD / 4) + tx];
        u64 aa[4] = { pk2(a0.x, a1.x), pk2(a0.y, a1.y),
                      pk2(a0.z, a1.z), pk2(a0.w, a1.w) };
        u64 gg[4] = { pk2(g0.x, g1.x), pk2(g0.y, g1.y),
                      pk2(g0.z, g1.z), pk2(g0.w, g1.w) };
#pragma unroll
        for (int i = 0; i < 4; i++)
#pragma unroll
            for (int j = 0; j < 4; j++)
                ffma2(acc2[i][j], aa[i], gg[j]);
    }

#pragma unroll
    for (int i = 0; i < 4; i++) {
        int r = ty * 4 + i;
        int row = row0 + r;
        if (row >= nrows) continue;
        float4 o;
        float* op = &o.x;
#pragma unroll
        for (int j = 0; j < 4; j++) {
            int col = tx * 4 + j;
            float z = red2(acc2[i][j]);
            float gate = 1.f / (1.f + __expf(-z));
            float a = As[col * GPAD + r];
            float b = As[(col + 64) * GPAD + r];
            op[j] = (MODE == 1) ? (gate * b + (1.f - gate) * a)
                                : (gate * a + (1.f - gate) * b);
        }
        *(float4*)(out + (size_t)row * D + tx * 4) = o;
    }
}

// ---------------- tail rows: out = agg / max(cnt, 1) ------------------------
template <int MODE>
__global__ void normalize_rows(float* __restrict__ out, int row0, int row_end)
{
    const float* agg = (MODE == 0) ? g_eagg  : g_aagg;
    const float* cnt = (MODE == 0) ? g_cnt_e : g_cnt_a;
    int gid = blockIdx.x * blockDim.x + threadIdx.x;
    int n = (row_end - row0) * DV4;
    if (gid >= n) return;
    int r = row0 + (gid >> 4);
    int c = gid & 15;
    float ic = 1.f / fmaxf(__ldg(cnt + r), 1.f);
    float4 v = ((const float4*)agg)[(size_t)r * DV4 + c];
    ((float4*)out)[(size_t)r * DV4 + c] =
        make_float4(v.x * ic, v.y * ic, v.z * ic, v.w * ic);
}

// ---------------- launch -----------------------------------------------------
extern "C" void kernel_launch(void* const* d_in, const int* in_sizes, int n_in,
                              void* d_out, int out_size)
{
    const float* entity_emb = (const float*)d_in[0];
    const float* user_emb   = (const float*)d_in[1];
    const float* weight     = (const float*)d_in[2];
    const float* gate1_w    = (const float*)d_in[3];
    const float* gate2_w    = (const float*)d_in[4];
    const float* gate3_w    = (const float*)d_in[5];
    const int*   edge_index = (const int*)d_in[6];
    const int*   edge_type  = (const int*)d_in[7];
    const int*   uedge_index= (const int*)d_in[8];
    const int*   uedge_type = (const int*)d_in[9];
    const int*   mat_row    = (const int*)d_in[10];
    const int*   mat_col    = (const int*)d_in[11];

    int n_e  = in_sizes[7];    // 1,500,000
    int n_ue = in_sizes[9];    // 1,000,000
    int n_m  = in_sizes[10];   // 1,500,000

    float* out = (float*)d_out;
    float* user_out = out + (size_t)N_ENTITIES * D;

    // opt-in >48KB dynamic smem (idempotent, capture-safe: no stream work)
    cudaFuncSetAttribute(gate_fuse<0>, cudaFuncAttributeMaxDynamicSharedMemorySize, GATE_SMEM);
    cudaFuncSetAttribute(gate_fuse<1>, cudaFuncAttributeMaxDynamicSharedMemorySize, GATE_SMEM);

    zero_all<<<2048, 256>>>();

    const int SG = 4736;   // 32 blocks/SM worth of grid-stride scatter blocks
    scatter_entity<<<SG, 256>>>((const float4*)entity_emb, (const float4*)weight,
                                edge_index, edge_index + n_e, edge_type, n_e);
    scatter_userkg<<<SG, 256>>>((const float4*)user_emb, (const float4*)weight,
                                uedge_index, uedge_index + n_ue, uedge_type, n_ue);
    scatter_mat<<<SG, 256>>>((const float4*)user_emb, (const float4*)entity_emb,
                             (const float4*)weight, mat_row, mat_col, n_m);

    gate_fuse<0><<<(N_ITEMS + 63) / 64, 256, GATE_SMEM>>>(gate1_w, gate2_w, out, N_ITEMS);
    gate_fuse<1><<<(N_USERS + 63) / 64, 256, GATE_SMEM>>>(gate2_w, gate3_w, user_out, N_USERS);

    {
        int n = (N_ENTITIES - N_ITEMS) * DV4;
        normalize_rows<0><<<(n + 255) / 256, 256>>>(out, N_ITEMS, N_ENTITIES);
    }
    {
        int n = (N_USER_NODES - N_USERS) * DV4;
        normalize_rows<1><<<(n + 255) / 256, 256>>>(user_out, N_USERS, N_USER_NODES);
    }
}

// round 9
// speedup vs baseline: 1.0628x; 1.0560x over previous
#include <cuda_runtime.h>
#include <math.h>

#define N_USERS      100000
#define N_ITEMS      50000
#define N_ENTITIES   180000
#define N_USER_NODES 150000
#define N_REL        32
#define D            64
#define DV4          16   // D/4 float4 chunks per row

// ---------------- scratch (device globals; no allocation allowed) ----------
__device__ float g_eagg[(size_t)N_ENTITIES * D];      // entity_agg sums
__device__ float g_aagg[(size_t)N_USER_NODES * D];    // attribute_agg sums
__device__ float g_iu  [(size_t)N_ITEMS * D];         // i_u_agg sums
__device__ float g_ui  [(size_t)N_USERS * D];         // u_i_agg sums
__device__ float g_cnt_e [N_ENTITIES];
__device__ float g_cnt_a [N_USER_NODES];
__device__ float g_cnt_iu[N_ITEMS];
__device__ float g_cnt_ui[N_USERS];

__device__ __forceinline__ float4 mul4(float4 a, float4 b) {
    return make_float4(a.x * b.x, a.y * b.y, a.z * b.z, a.w * b.w);
}

// ---------------- zero scratch each launch ---------------------------------
__global__ void zero_all() {
    int gid = blockIdx.x * blockDim.x + threadIdx.x;
    int stride = gridDim.x * blockDim.x;
    float4 z = make_float4(0.f, 0.f, 0.f, 0.f);
#define ZLOOP(arr, n4) { float4* p = (float4*)(arr); \
    for (int i = gid; i < (n4); i += stride) p[i] = z; }
    ZLOOP(g_eagg, N_ENTITIES * DV4)
    ZLOOP(g_aagg, N_USER_NODES * DV4)
    ZLOOP(g_iu,   N_ITEMS * DV4)
    ZLOOP(g_ui,   N_USERS * DV4)
    ZLOOP(g_cnt_e,  N_ENTITIES / 4)
    ZLOOP(g_cnt_a,  N_USER_NODES / 4)
    ZLOOP(g_cnt_iu, N_ITEMS / 4)
    ZLOOP(g_cnt_ui, N_USERS / 4)
#undef ZLOOP
}

// ---------------- typed scatter body (index-prefetch pipeline) -------------
// 16 lanes per edge (one float4 chunk each). Index loads for iteration i+1
// are issued BEFORE the gather of iteration i.
__device__ __forceinline__ void scatter_body_pf(
    const float4* __restrict__ emb, const float4* __restrict__ sw,
    const int* __restrict__ head, const int* __restrict__ tail,
    const int* __restrict__ etype,
    float4* __restrict__ agg, float* __restrict__ cnt, int n_edges,
    int blk, int nblocks)
{
    int gid = blk * 256 + threadIdx.x;
    int c = gid & 15;
    int stride = nblocks * 256;
    int total = n_edges << 4;

    int g = gid;
    if (g >= total) return;
    int e = g >> 4;
    int h  = __ldg(head + e);
    int t  = __ldg(tail + e);
    int ty = __ldg(etype + e);

    while (true) {
        int gn = g + stride;
        bool more = gn < total;
        int hn = 0, tn = 0, tyn = 0;
        if (more) {
            int en = gn >> 4;
            hn  = __ldg(head + en);
            tn  = __ldg(tail + en);
            tyn = __ldg(etype + en);
        }
        float4 v = __ldg(emb + t * DV4 + c);
        float4 w = sw[ty * DV4 + c];
        atomicAdd(agg + h * DV4 + c, mul4(v, w));
        if (c == 0) atomicAdd(cnt + h, 1.0f);
        if (!more) break;
        g = gn; h = hn; t = tn; ty = tyn;
    }
}

// mat body: two independent gather->RED chains per edge
__device__ __forceinline__ void scatter_mat_body(
    const float4* __restrict__ uemb, const float4* __restrict__ eemb,
    float4 w0, const int* __restrict__ mrow, const int* __restrict__ mcol,
    int n, int blk, int nblocks)
{
    int gid = blk * 256 + threadIdx.x;
    int c = gid & 15;
    int stride = nblocks * 256;
    float4* iu = (float4*)g_iu;
    float4* ui = (float4*)g_ui;
    int total = n << 4;

    int g = gid;
    if (g >= total) return;
    int e = g >> 4;
    int r  = __ldg(mrow + e);
    int cl = __ldg(mcol + e);

    while (true) {
        int gn = g + stride;
        bool more = gn < total;
        int rn = 0, cln = 0;
        if (more) {
            int en = gn >> 4;
            rn  = __ldg(mrow + en);
            cln = __ldg(mcol + en);
        }
        float4 uv = __ldg(uemb + r  * DV4 + c);
        float4 ev = __ldg(eemb + cl * DV4 + c);
        atomicAdd(iu + cl * DV4 + c, mul4(uv, w0));
        atomicAdd(ui + r  * DV4 + c, mul4(ev, w0));
        if (c == 0) {
            atomicAdd(g_cnt_iu + cl, 1.0f);
            atomicAdd(g_cnt_ui + r,  1.0f);
        }
        if (!more) break;
        g = gn; r = rn; cl = cln;
    }
}

// ---------------- fused scatter: all three workloads in one wave -----------
// Block partitions sized by L2-traffic share so the LTS-saturating mat
// partition runs concurrently with the latency-bound kg partitions.
__global__ void __launch_bounds__(256, 8)
scatter_all(const float4* __restrict__ eemb, const float4* __restrict__ uemb,
            const float4* __restrict__ weight,
            const int* __restrict__ e_head, const int* __restrict__ e_tail,
            const int* __restrict__ e_type, int n_e,
            const int* __restrict__ u_head, const int* __restrict__ u_tail,
            const int* __restrict__ u_type, int n_ue,
            const int* __restrict__ mrow, const int* __restrict__ mcol, int n_m,
            int b_e, int b_u)
{
    __shared__ float4 sw[N_REL * DV4];
    int b = blockIdx.x;
    if (b < b_u) {    // kg partitions need the full relation table
        for (int i = threadIdx.x; i < N_REL * DV4; i += blockDim.x)
            sw[i] = __ldg(weight + i);
    }
    __syncthreads();

    if (b < b_e) {
        scatter_body_pf(eemb, sw, e_head, e_tail, e_type,
                        (float4*)g_eagg, g_cnt_e, n_e, b, b_e);
    } else if (b < b_u) {
        scatter_body_pf(uemb, sw, u_head, u_tail, u_type,
                        (float4*)g_aagg, g_cnt_a, n_ue, b - b_e, b_u - b_e);
    } else {
        float4 w0 = __ldg(weight + (threadIdx.x & 15));  // weight[0] chunk
        scatter_mat_body(uemb, eemb, w0, mrow, mcol, n_m,
                         b - b_u, gridDim.x - b_u);
    }
}

// ---------------- gated fusion: sigmoid(A@GA^T + B@GB^T) blend --------------
// (scalar-FFMA version from the 479.7us run)
#define GPAD 68
#define GATE_SMEM ((2 * 128 * GPAD + 128) * 4)

template <int MODE>
__global__ void gate_fuse(const float* __restrict__ GA,
                          const float* __restrict__ GB,
                          float* __restrict__ out, int nrows)
{
    const float* aggA = (MODE == 0) ? g_eagg   : g_ui;
    const float* cntA = (MODE == 0) ? g_cnt_e  : g_cnt_ui;
    const float* aggB = (MODE == 0) ? g_iu     : g_aagg;
    const float* cntB = (MODE == 0) ? g_cnt_iu : g_cnt_a;

    extern __shared__ float sm[];
    float* As   = sm;                    // [128][GPAD]  (A|B transposed, normalized)
    float* Gs   = sm + 128 * GPAD;       // [128][GPAD]  (GA^T ; GB^T)
    float* invA = Gs + 128 * GPAD;       // [64]
    float* invB = invA + 64;             // [64]

    int tid = threadIdx.x;
    int row0 = blockIdx.x * 64;

    if (tid < 64) {
        int r = row0 + tid;
        invA[tid] = (r < nrows) ? 1.f / fmaxf(__ldg(cntA + r), 1.f) : 0.f;
    } else if (tid < 128) {
        int r = row0 + tid - 64;
        invB[tid - 64] = (r < nrows) ? 1.f / fmaxf(__ldg(cntB + r), 1.f) : 0.f;
    }
    __syncthreads();

    for (int idx = tid; idx < 64 * 64; idx += 256) {
        int r = idx >> 6, k = idx & 63;
        int row = row0 + r;
        float a = 0.f, b = 0.f;
        if (row < nrows) {
            a = aggA[(size_t)row * D + k] * invA[r];
            b = aggB[(size_t)row * D + k] * invB[r];
        }
        As[k * GPAD + r]        = a;
        As[(k + 64) * GPAD + r] = b;
    }
    for (int idx = tid; idx < 64 * 64; idx += 256) {
        int j = idx >> 6, k = idx & 63;          // GA[j*64+k] read coalesced
        Gs[k * GPAD + j]        = __ldg(GA + idx);
        Gs[(k + 64) * GPAD + j] = __ldg(GB + idx);
    }
    __syncthreads();

    int tx = tid & 15, ty = tid >> 4;
    float acc[4][4] = {};
    const float4* As4 = (const float4*)As;
    const float4* Gs4 = (const float4*)Gs;
#pragma unroll 4
    for (int k = 0; k < 128; k++) {
        float4 av = As4[k * (GPAD / 4) + ty];
        float4 gv = Gs4[k * (GPAD / 4) + tx];
        float a_[4] = {av.x, av.y, av.z, av.w};
        float g_[4] = {gv.x, gv.y, gv.z, gv.w};
#pragma unroll
        for (int i = 0; i < 4; i++)
#pragma unroll
            for (int j = 0; j < 4; j++)
                acc[i][j] += a_[i] * g_[j];
    }

#pragma unroll
    for (int i = 0; i < 4; i++) {
        int r = ty * 4 + i;
        int row = row0 + r;
        if (row >= nrows) continue;
        float4 o;
        float* op = &o.x;
#pragma unroll
        for (int j = 0; j < 4; j++) {
            int col = tx * 4 + j;
            float gate = 1.f / (1.f + __expf(-acc[i][j]));
            float a = As[col * GPAD + r];
            float b = As[(col + 64) * GPAD + r];
            op[j] = (MODE == 1) ? (gate * b + (1.f - gate) * a)
                                : (gate * a + (1.f - gate) * b);
        }
        *(float4*)(out + (size_t)row * D + tx * 4) = o;
    }
}

// ---------------- tail rows: out = agg / max(cnt, 1) ------------------------
template <int MODE>
__global__ void normalize_rows(float* __restrict__ out, int row0, int row_end)
{
    const float* agg = (MODE == 0) ? g_eagg  : g_aagg;
    const float* cnt = (MODE == 0) ? g_cnt_e : g_cnt_a;
    int gid = blockIdx.x * blockDim.x + threadIdx.x;
    int n = (row_end - row0) * DV4;
    if (gid >= n) return;
    int r = row0 + (gid >> 4);
    int c = gid & 15;
    float ic = 1.f / fmaxf(__ldg(cnt + r), 1.f);
    float4 v = ((const float4*)agg)[(size_t)r * DV4 + c];
    ((float4*)out)[(size_t)r * DV4 + c] =
        make_float4(v.x * ic, v.y * ic, v.z * ic, v.w * ic);
}

// ---------------- launch -----------------------------------------------------
extern "C" void kernel_launch(void* const* d_in, const int* in_sizes, int n_in,
                              void* d_out, int out_size)
{
    const float* entity_emb = (const float*)d_in[0];
    const float* user_emb   = (const float*)d_in[1];
    const float* weight     = (const float*)d_in[2];
    const float* gate1_w    = (const float*)d_in[3];
    const float* gate2_w    = (const float*)d_in[4];
    const float* gate3_w    = (const float*)d_in[5];
    const int*   edge_index = (const int*)d_in[6];
    const int*   edge_type  = (const int*)d_in[7];
    const int*   uedge_index= (const int*)d_in[8];
    const int*   uedge_type = (const int*)d_in[9];
    const int*   mat_row    = (const int*)d_in[10];
    const int*   mat_col    = (const int*)d_in[11];

    int n_e  = in_sizes[7];    // 1,500,000
    int n_ue = in_sizes[9];    // 1,000,000
    int n_m  = in_sizes[10];   // 1,500,000

    float* out = (float*)d_out;
    float* user_out = out + (size_t)N_ENTITIES * D;

    cudaFuncSetAttribute(gate_fuse<0>, cudaFuncAttributeMaxDynamicSharedMemorySize, GATE_SMEM);
    cudaFuncSetAttribute(gate_fuse<1>, cudaFuncAttributeMaxDynamicSharedMemorySize, GATE_SMEM);

    zero_all<<<2048, 256>>>();

    // Partition blocks by L2-traffic share:
    //   kg edge:  256B gather + 256B RED + 12B idx = 524B
    //   mat edge: 2*256 + 2*256 + 8B idx          = 1032B
    const int SG = 4736;
    double t_e = (double)n_e * 524.0;
    double t_u = (double)n_ue * 524.0;
    double t_m = (double)n_m * 1032.0;
    double tot = t_e + t_u + t_m;
    int b_e = (int)(SG * (t_e / tot) + 0.5);
    int b_u = b_e + (int)(SG * (t_u / tot) + 0.5);
    if (b_e < 1) b_e = 1;
    if (b_u <= b_e) b_u = b_e + 1;
    if (b_u >= SG) b_u = SG - 1;

    scatter_all<<<SG, 256>>>((const float4*)entity_emb, (const float4*)user_emb,
                             (const float4*)weight,
                             edge_index, edge_index + n_e, edge_type, n_e,
                             uedge_index, uedge_index + n_ue, uedge_type, n_ue,
                             mat_row, mat_col, n_m,
                             b_e, b_u);

    gate_fuse<0><<<(N_ITEMS + 63) / 64, 256, GATE_SMEM>>>(gate1_w, gate2_w, out, N_ITEMS);
    gate_fuse<1><<<(N_USERS + 63) / 64, 256, GATE_SMEM>>>(gate2_w, gate3_w, user_out, N_USERS);

    {
        int n = (N_ENTITIES - N_ITEMS) * DV4;
        normalize_rows<0><<<(n + 255) / 256, 256>>>(out, N_ITEMS, N_ENTITIES);
    }
    {
        int n = (N_USER_NODES - N_USERS) * DV4;
        normalize_rows<1><<<(n + 255) / 256, 256>>>(user_out, N_USERS, N_USER_NODES);
    }
}

// round 10
// speedup vs baseline: 1.0664x; 1.0034x over previous
#include <cuda_runtime.h>
#include <math.h>

#define N_USERS      100000
#define N_ITEMS      50000
#define N_ENTITIES   180000
#define N_USER_NODES 150000
#define N_REL        32
#define D            64
#define DV4          16   // D/4 float4 chunks per row

// ---------------- scratch (device globals; no allocation allowed) ----------
__device__ float g_eagg[(size_t)N_ENTITIES * D];      // entity_agg sums
__device__ float g_aagg[(size_t)N_USER_NODES * D];    // attribute_agg sums
__device__ float g_iu  [(size_t)N_ITEMS * D];         // i_u_agg sums
__device__ float g_ui  [(size_t)N_USERS * D];         // u_i_agg sums
__device__ float g_cnt_e [N_ENTITIES];
__device__ float g_cnt_a [N_USER_NODES];
__device__ float g_cnt_iu[N_ITEMS];
__device__ float g_cnt_ui[N_USERS];

__device__ __forceinline__ float4 mul4(float4 a, float4 b) {
    return make_float4(a.x * b.x, a.y * b.y, a.z * b.z, a.w * b.w);
}

// ---------------- zero scratch each launch ---------------------------------
__global__ void zero_all() {
    int gid = blockIdx.x * blockDim.x + threadIdx.x;
    int stride = gridDim.x * blockDim.x;
    float4 z = make_float4(0.f, 0.f, 0.f, 0.f);
#define ZLOOP(arr, n4) { float4* p = (float4*)(arr); \
    for (int i = gid; i < (n4); i += stride) p[i] = z; }
    ZLOOP(g_eagg, N_ENTITIES * DV4)
    ZLOOP(g_aagg, N_USER_NODES * DV4)
    ZLOOP(g_iu,   N_ITEMS * DV4)
    ZLOOP(g_ui,   N_USERS * DV4)
    ZLOOP(g_cnt_e,  N_ENTITIES / 4)
    ZLOOP(g_cnt_a,  N_USER_NODES / 4)
    ZLOOP(g_cnt_iu, N_ITEMS / 4)
    ZLOOP(g_cnt_ui, N_USERS / 4)
#undef ZLOOP
}

// ---------------- typed scatter body (index-prefetch pipeline) -------------
// 16 lanes per edge (one float4 chunk each). Index loads for iteration i+1
// are issued BEFORE the gather of iteration i.
__device__ __forceinline__ void scatter_body_pf(
    const float4* __restrict__ emb, const float4* __restrict__ sw,
    const int* __restrict__ head, const int* __restrict__ tail,
    const int* __restrict__ etype,
    float4* __restrict__ agg, float* __restrict__ cnt, int n_edges,
    int blk, int nblocks)
{
    int gid = blk * 256 + threadIdx.x;
    int c = gid & 15;
    int stride = nblocks * 256;
    int total = n_edges << 4;

    int g = gid;
    if (g >= total) return;
    int e = g >> 4;
    int h  = __ldg(head + e);
    int t  = __ldg(tail + e);
    int ty = __ldg(etype + e);

    while (true) {
        int gn = g + stride;
        bool more = gn < total;
        int hn = 0, tn = 0, tyn = 0;
        if (more) {
            int en = gn >> 4;
            hn  = __ldg(head + en);
            tn  = __ldg(tail + en);
            tyn = __ldg(etype + en);
        }
        float4 v = __ldg(emb + t * DV4 + c);
        float4 w = sw[ty * DV4 + c];
        atomicAdd(agg + h * DV4 + c, mul4(v, w));
        if (c == 0) atomicAdd(cnt + h, 1.0f);
        if (!more) break;
        g = gn; h = hn; t = tn; ty = tyn;
    }
}

// mat body: two independent gather->RED chains per edge
__device__ __forceinline__ void scatter_mat_body(
    const float4* __restrict__ uemb, const float4* __restrict__ eemb,
    float4 w0, const int* __restrict__ mrow, const int* __restrict__ mcol,
    int n, int blk, int nblocks)
{
    int gid = blk * 256 + threadIdx.x;
    int c = gid & 15;
    int stride = nblocks * 256;
    float4* iu = (float4*)g_iu;
    float4* ui = (float4*)g_ui;
    int total = n << 4;

    int g = gid;
    if (g >= total) return;
    int e = g >> 4;
    int r  = __ldg(mrow + e);
    int cl = __ldg(mcol + e);

    while (true) {
        int gn = g + stride;
        bool more = gn < total;
        int rn = 0, cln = 0;
        if (more) {
            int en = gn >> 4;
            rn  = __ldg(mrow + en);
            cln = __ldg(mcol + en);
        }
        float4 uv = __ldg(uemb + r  * DV4 + c);
        float4 ev = __ldg(eemb + cl * DV4 + c);
        atomicAdd(iu + cl * DV4 + c, mul4(uv, w0));
        atomicAdd(ui + r  * DV4 + c, mul4(ev, w0));
        if (c == 0) {
            atomicAdd(g_cnt_iu + cl, 1.0f);
            atomicAdd(g_cnt_ui + r,  1.0f);
        }
        if (!more) break;
        g = gn; r = rn; cl = cln;
    }
}

// ---------------- fused scatter: all three workloads in one wave -----------
// Block partitions sized by L2-traffic share so the LTS-saturating mat
// partition runs concurrently with the latency-bound kg partitions.
__global__ void __launch_bounds__(256, 8)
scatter_all(const float4* __restrict__ eemb, const float4* __restrict__ uemb,
            const float4* __restrict__ weight,
            const int* __restrict__ e_head, const int* __restrict__ e_tail,
            const int* __restrict__ e_type, int n_e,
            const int* __restrict__ u_head, const int* __restrict__ u_tail,
            const int* __restrict__ u_type, int n_ue,
            const int* __restrict__ mrow, const int* __restrict__ mcol, int n_m,
            int b_e, int b_u)
{
    __shared__ float4 sw[N_REL * DV4];
    int b = blockIdx.x;
    if (b < b_u) {    // kg partitions need the full relation table
        for (int i = threadIdx.x; i < N_REL * DV4; i += blockDim.x)
            sw[i] = __ldg(weight + i);
    }
    __syncthreads();

    if (b < b_e) {
        scatter_body_pf(eemb, sw, e_head, e_tail, e_type,
                        (float4*)g_eagg, g_cnt_e, n_e, b, b_e);
    } else if (b < b_u) {
        scatter_body_pf(uemb, sw, u_head, u_tail, u_type,
                        (float4*)g_aagg, g_cnt_a, n_ue, b - b_e, b_u - b_e);
    } else {
        float4 w0 = __ldg(weight + (threadIdx.x & 15));  // weight[0] chunk
        scatter_mat_body(uemb, eemb, w0, mrow, mcol, n_m,
                         b - b_u, gridDim.x - b_u);
    }
}

// ---------------- gated fusion: sigmoid(A@GA^T + B@GB^T) blend --------------
// (scalar-FFMA version from the 479.7us run)
#define GPAD 68
#define GATE_SMEM ((2 * 128 * GPAD + 128) * 4)

template <int MODE>
__global__ void gate_fuse(const float* __restrict__ GA,
                          const float* __restrict__ GB,
                          float* __restrict__ out, int nrows)
{
    const float* aggA = (MODE == 0) ? g_eagg   : g_ui;
    const float* cntA = (MODE == 0) ? g_cnt_e  : g_cnt_ui;
    const float* aggB = (MODE == 0) ? g_iu     : g_aagg;
    const float* cntB = (MODE == 0) ? g_cnt_iu : g_cnt_a;

    extern __shared__ float sm[];
    float* As   = sm;                    // [128][GPAD]  (A|B transposed, normalized)
    float* Gs   = sm + 128 * GPAD;       // [128][GPAD]  (GA^T ; GB^T)
    float* invA = Gs + 128 * GPAD;       // [64]
    float* invB = invA + 64;             // [64]

    int tid = threadIdx.x;
    int row0 = blockIdx.x * 64;

    if (tid < 64) {
        int r = row0 + tid;
        invA[tid] = (r < nrows) ? 1.f / fmaxf(__ldg(cntA + r), 1.f) : 0.f;
    } else if (tid < 128) {
        int r = row0 + tid - 64;
        invB[tid - 64] = (r < nrows) ? 1.f / fmaxf(__ldg(cntB + r), 1.f) : 0.f;
    }
    __syncthreads();

    for (int idx = tid; idx < 64 * 64; idx += 256) {
        int r = idx >> 6, k = idx & 63;
        int row = row0 + r;
        float a = 0.f, b = 0.f;
        if (row < nrows) {
            a = aggA[(size_t)row * D + k] * invA[r];
            b = aggB[(size_t)row * D + k] * invB[r];
        }
        As[k * GPAD + r]        = a;
        As[(k + 64) * GPAD + r] = b;
    }
    for (int idx = tid; idx < 64 * 64; idx += 256) {
        int j = idx >> 6, k = idx & 63;          // GA[j*64+k] read coalesced
        Gs[k * GPAD + j]        = __ldg(GA + idx);
        Gs[(k + 64) * GPAD + j] = __ldg(GB + idx);
    }
    __syncthreads();

    int tx = tid & 15, ty = tid >> 4;
    float acc[4][4] = {};
    const float4* As4 = (const float4*)As;
    const float4* Gs4 = (const float4*)Gs;
#pragma unroll 4
    for (int k = 0; k < 128; k++) {
        float4 av = As4[k * (GPAD / 4) + ty];
        float4 gv = Gs4[k * (GPAD / 4) + tx];
        float a_[4] = {av.x, av.y, av.z, av.w};
        float g_[4] = {gv.x, gv.y, gv.z, gv.w};
#pragma unroll
        for (int i = 0; i < 4; i++)
#pragma unroll
            for (int j = 0; j < 4; j++)
                acc[i][j] += a_[i] * g_[j];
    }

#pragma unroll
    for (int i = 0; i < 4; i++) {
        int r = ty * 4 + i;
        int row = row0 + r;
        if (row >= nrows) continue;
        float4 o;
        float* op = &o.x;
#pragma unroll
        for (int j = 0; j < 4; j++) {
            int col = tx * 4 + j;
            float gate = 1.f / (1.f + __expf(-acc[i][j]));
            float a = As[col * GPAD + r];
            float b = As[(col + 64) * GPAD + r];
            op[j] = (MODE == 1) ? (gate * b + (1.f - gate) * a)
                                : (gate * a + (1.f - gate) * b);
        }
        *(float4*)(out + (size_t)row * D + tx * 4) = o;
    }
}

// ---------------- tail rows: out = agg / max(cnt, 1) ------------------------
template <int MODE>
__global__ void normalize_rows(float* __restrict__ out, int row0, int row_end)
{
    const float* agg = (MODE == 0) ? g_eagg  : g_aagg;
    const float* cnt = (MODE == 0) ? g_cnt_e : g_cnt_a;
    int gid = blockIdx.x * blockDim.x + threadIdx.x;
    int n = (row_end - row0) * DV4;
    if (gid >= n) return;
    int r = row0 + (gid >> 4);
    int c = gid & 15;
    float ic = 1.f / fmaxf(__ldg(cnt + r), 1.f);
    float4 v = ((const float4*)agg)[(size_t)r * DV4 + c];
    ((float4*)out)[(size_t)r * DV4 + c] =
        make_float4(v.x * ic, v.y * ic, v.z * ic, v.w * ic);
}

// ---------------- launch -----------------------------------------------------
extern "C" void kernel_launch(void* const* d_in, const int* in_sizes, int n_in,
                              void* d_out, int out_size)
{
    const float* entity_emb = (const float*)d_in[0];
    const float* user_emb   = (const float*)d_in[1];
    const float* weight     = (const float*)d_in[2];
    const float* gate1_w    = (const float*)d_in[3];
    const float* gate2_w    = (const float*)d_in[4];
    const float* gate3_w    = (const float*)d_in[5];
    const int*   edge_index = (const int*)d_in[6];
    const int*   edge_type  = (const int*)d_in[7];
    const int*   uedge_index= (const int*)d_in[8];
    const int*   uedge_type = (const int*)d_in[9];
    const int*   mat_row    = (const int*)d_in[10];
    const int*   mat_col    = (const int*)d_in[11];

    int n_e  = in_sizes[7];    // 1,500,000
    int n_ue = in_sizes[9];    // 1,000,000
    int n_m  = in_sizes[10];   // 1,500,000

    float* out = (float*)d_out;
    float* user_out = out + (size_t)N_ENTITIES * D;

    cudaFuncSetAttribute(gate_fuse<0>, cudaFuncAttributeMaxDynamicSharedMemorySize, GATE_SMEM);
    cudaFuncSetAttribute(gate_fuse<1>, cudaFuncAttributeMaxDynamicSharedMemorySize, GATE_SMEM);

    zero_all<<<2048, 256>>>();

    // Partition blocks by L2-traffic share:
    //   kg edge:  256B gather + 256B RED + 12B idx = 524B
    //   mat edge: 2*256 + 2*256 + 8B idx          = 1032B
    const int SG = 4736;
    double t_e = (double)n_e * 524.0;
    double t_u = (double)n_ue * 524.0;
    double t_m = (double)n_m * 1032.0;
    double tot = t_e + t_u + t_m;
    int b_e = (int)(SG * (t_e / tot) + 0.5);
    int b_u = b_e + (int)(SG * (t_u / tot) + 0.5);
    if (b_e < 1) b_e = 1;
    if (b_u <= b_e) b_u = b_e + 1;
    if (b_u >= SG) b_u = SG - 1;

    scatter_all<<<SG, 256>>>((const float4*)entity_emb, (const float4*)user_emb,
                             (const float4*)weight,
                             edge_index, edge_index + n_e, edge_type, n_e,
                             uedge_index, uedge_index + n_ue, uedge_type, n_ue,
                             mat_row, mat_col, n_m,
                             b_e, b_u);

    gate_fuse<0><<<(N_ITEMS + 63) / 64, 256, GATE_SMEM>>>(gate1_w, gate2_w, out, N_ITEMS);
    gate_fuse<1><<<(N_USERS + 63) / 64, 256, GATE_SMEM>>>(gate2_w, gate3_w, user_out, N_USERS);

    {
        int n = (N_ENTITIES - N_ITEMS) * DV4;
        normalize_rows<0><<<(n + 255) / 256, 256>>>(out, N_ITEMS, N_ENTITIES);
    }
    {
        int n = (N_USER_NODES - N_USERS) * DV4;
        normalize_rows<1><<<(n + 255) / 256, 256>>>(user_out, N_USERS, N_USER_NODES);
    }
}

// round 11
// speedup vs baseline: 1.0819x; 1.0145x over previous
#include <cuda_runtime.h>
#include <math.h>

#define N_USERS      100000
#define N_ITEMS      50000
#define N_ENTITIES   180000
#define N_USER_NODES 150000
#define N_REL        32
#define D            64
#define DV4          16   // D/4 float4 chunks per row

// ---------------- scratch (device globals; no allocation allowed) ----------
__device__ float g_eagg[(size_t)N_ENTITIES * D];      // entity_agg sums
__device__ float g_aagg[(size_t)N_USER_NODES * D];    // attribute_agg sums
__device__ float g_iu  [(size_t)N_ITEMS * D];         // i_u_agg sums
__device__ float g_ui  [(size_t)N_USERS * D];         // u_i_agg sums
__device__ float g_cnt_e [N_ENTITIES];
__device__ float g_cnt_a [N_USER_NODES];
__device__ float g_cnt_iu[N_ITEMS];
__device__ float g_cnt_ui[N_USERS];

__device__ __forceinline__ float4 mul4(float4 a, float4 b) {
    return make_float4(a.x * b.x, a.y * b.y, a.z * b.z, a.w * b.w);
}

// ---------------- zero scratch each launch ---------------------------------
__global__ void zero_all() {
    int gid = blockIdx.x * blockDim.x + threadIdx.x;
    int stride = gridDim.x * blockDim.x;
    float4 z = make_float4(0.f, 0.f, 0.f, 0.f);
#define ZLOOP(arr, n4) { float4* p = (float4*)(arr); \
    for (int i = gid; i < (n4); i += stride) p[i] = z; }
    ZLOOP(g_eagg, N_ENTITIES * DV4)
    ZLOOP(g_aagg, N_USER_NODES * DV4)
    ZLOOP(g_iu,   N_ITEMS * DV4)
    ZLOOP(g_ui,   N_USERS * DV4)
    ZLOOP(g_cnt_e,  N_ENTITIES / 4)
    ZLOOP(g_cnt_a,  N_USER_NODES / 4)
    ZLOOP(g_cnt_iu, N_ITEMS / 4)
    ZLOOP(g_cnt_ui, N_USERS / 4)
#undef ZLOOP
}

// ---------------- typed scatter body (index-prefetch pipeline) -------------
__device__ __forceinline__ void scatter_body_pf(
    const float4* __restrict__ emb, const float4* __restrict__ sw,
    const int* __restrict__ head, const int* __restrict__ tail,
    const int* __restrict__ etype,
    float4* __restrict__ agg, float* __restrict__ cnt, int n_edges,
    int blk, int nblocks)
{
    int gid = blk * 256 + threadIdx.x;
    int c = gid & 15;
    int stride = nblocks * 256;
    int total = n_edges << 4;

    int g = gid;
    if (g >= total) return;
    int e = g >> 4;
    int h  = __ldg(head + e);
    int t  = __ldg(tail + e);
    int ty = __ldg(etype + e);

    while (true) {
        int gn = g + stride;
        bool more = gn < total;
        int hn = 0, tn = 0, tyn = 0;
        if (more) {
            int en = gn >> 4;
            hn  = __ldg(head + en);
            tn  = __ldg(tail + en);
            tyn = __ldg(etype + en);
        }
        float4 v = __ldg(emb + t * DV4 + c);
        float4 w = sw[ty * DV4 + c];
        atomicAdd(agg + h * DV4 + c, mul4(v, w));
        if (c == 0) atomicAdd(cnt + h, 1.0f);
        if (!more) break;
        g = gn; h = hn; t = tn; ty = tyn;
    }
}

__device__ __forceinline__ void scatter_mat_body(
    const float4* __restrict__ uemb, const float4* __restrict__ eemb,
    float4 w0, const int* __restrict__ mrow, const int* __restrict__ mcol,
    int n, int blk, int nblocks)
{
    int gid = blk * 256 + threadIdx.x;
    int c = gid & 15;
    int stride = nblocks * 256;
    float4* iu = (float4*)g_iu;
    float4* ui = (float4*)g_ui;
    int total = n << 4;

    int g = gid;
    if (g >= total) return;
    int e = g >> 4;
    int r  = __ldg(mrow + e);
    int cl = __ldg(mcol + e);

    while (true) {
        int gn = g + stride;
        bool more = gn < total;
        int rn = 0, cln = 0;
        if (more) {
            int en = gn >> 4;
            rn  = __ldg(mrow + en);
            cln = __ldg(mcol + en);
        }
        float4 uv = __ldg(uemb + r  * DV4 + c);
        float4 ev = __ldg(eemb + cl * DV4 + c);
        atomicAdd(iu + cl * DV4 + c, mul4(uv, w0));
        atomicAdd(ui + r  * DV4 + c, mul4(ev, w0));
        if (c == 0) {
            atomicAdd(g_cnt_iu + cl, 1.0f);
            atomicAdd(g_cnt_ui + r,  1.0f);
        }
        if (!more) break;
        g = gn; r = rn; cl = cln;
    }
}

// ---------------- fused scatter: all three workloads in one wave -----------
__global__ void __launch_bounds__(256, 8)
scatter_all(const float4* __restrict__ eemb, const float4* __restrict__ uemb,
            const float4* __restrict__ weight,
            const int* __restrict__ e_head, const int* __restrict__ e_tail,
            const int* __restrict__ e_type, int n_e,
            const int* __restrict__ u_head, const int* __restrict__ u_tail,
            const int* __restrict__ u_type, int n_ue,
            const int* __restrict__ mrow, const int* __restrict__ mcol, int n_m,
            int b_e, int b_u)
{
    __shared__ float4 sw[N_REL * DV4];
    int b = blockIdx.x;
    if (b < b_u) {
        for (int i = threadIdx.x; i < N_REL * DV4; i += blockDim.x)
            sw[i] = __ldg(weight + i);
    }
    __syncthreads();

    if (b < b_e) {
        scatter_body_pf(eemb, sw, e_head, e_tail, e_type,
                        (float4*)g_eagg, g_cnt_e, n_e, b, b_e);
    } else if (b < b_u) {
        scatter_body_pf(uemb, sw, u_head, u_tail, u_type,
                        (float4*)g_aagg, g_cnt_a, n_ue, b - b_e, b_u - b_e);
    } else {
        float4 w0 = __ldg(weight + (threadIdx.x & 15));
        scatter_mat_body(uemb, eemb, w0, mrow, mcol, n_m,
                         b - b_u, gridDim.x - b_u);
    }
}

// ---------------- gated fusion, K-split two-stage ----------------------------
// Z = A@GA^T + B@GB^T done as two K=64 stages sharing one operand buffer.
// Stage A stashes each thread's 16 blend a-values in registers before the
// buffer is overwritten by B. Smem: 64*GPAD*2 + 128 floats = ~34.5KB ->
// 5+ blocks/SM instead of 3.
#define GPAD 68
#define GATE_SMEM ((2 * 64 * GPAD + 128) * 4)

__device__ __forceinline__ void gate_body(
    const float* __restrict__ aggA, const float* __restrict__ cntA,
    const float* __restrict__ aggB, const float* __restrict__ cntB,
    const float* __restrict__ GA,   const float* __restrict__ GB,
    float* __restrict__ out, int nrows, int blk, int mode)
{
    extern __shared__ float sm[];
    float* As   = sm;               // [64][GPAD] current-stage operand^T
    float* Gs   = sm + 64 * GPAD;   // [64][GPAD] current-stage gate^T
    float* invA = Gs + 64 * GPAD;   // [64]
    float* invB = invA + 64;        // [64]

    int tid = threadIdx.x;
    int row0 = blk * 64;

    if (tid < 64) {
        int r = row0 + tid;
        invA[tid] = (r < nrows) ? 1.f / fmaxf(__ldg(cntA + r), 1.f) : 0.f;
    } else if (tid < 128) {
        int r = row0 + tid - 64;
        invB[tid - 64] = (r < nrows) ? 1.f / fmaxf(__ldg(cntB + r), 1.f) : 0.f;
    }
    __syncthreads();

    int tx = tid & 15, ty = tid >> 4;
    const float4* As4 = (const float4*)As;
    const float4* Gs4 = (const float4*)Gs;
    float acc[4][4] = {};
    float ast[4][4];

    // ---- stage A: operand = aggA/invA, gate = GA ----
    for (int idx = tid; idx < 64 * 64; idx += 256) {
        int r = idx >> 6, k = idx & 63;
        int row = row0 + r;
        As[k * GPAD + r] = (row < nrows) ? aggA[(size_t)row * D + k] * invA[r] : 0.f;
    }
    for (int idx = tid; idx < 64 * 64; idx += 256) {
        int j = idx >> 6, k = idx & 63;
        Gs[k * GPAD + j] = __ldg(GA + idx);
    }
    __syncthreads();

#pragma unroll
    for (int j = 0; j < 4; j++) {       // stash a-values (vectorized along r)
        float4 v = As4[(tx * 4 + j) * (GPAD / 4) + ty];
        ast[0][j] = v.x; ast[1][j] = v.y; ast[2][j] = v.z; ast[3][j] = v.w;
    }
#pragma unroll 4
    for (int k = 0; k < 64; k++) {
        float4 av = As4[k * (GPAD / 4) + ty];
        float4 gv = Gs4[k * (GPAD / 4) + tx];
        float a_[4] = {av.x, av.y, av.z, av.w};
        float g_[4] = {gv.x, gv.y, gv.z, gv.w};
#pragma unroll
        for (int i = 0; i < 4; i++)
#pragma unroll
            for (int j = 0; j < 4; j++)
                acc[i][j] += a_[i] * g_[j];
    }
    __syncthreads();

    // ---- stage B: operand = aggB/invB, gate = GB ----
    for (int idx = tid; idx < 64 * 64; idx += 256) {
        int r = idx >> 6, k = idx & 63;
        int row = row0 + r;
        As[k * GPAD + r] = (row < nrows) ? aggB[(size_t)row * D + k] * invB[r] : 0.f;
    }
    for (int idx = tid; idx < 64 * 64; idx += 256) {
        int j = idx >> 6, k = idx & 63;
        Gs[k * GPAD + j] = __ldg(GB + idx);
    }
    __syncthreads();

#pragma unroll 4
    for (int k = 0; k < 64; k++) {
        float4 av = As4[k * (GPAD / 4) + ty];
        float4 gv = Gs4[k * (GPAD / 4) + tx];
        float a_[4] = {av.x, av.y, av.z, av.w};
        float g_[4] = {gv.x, gv.y, gv.z, gv.w};
#pragma unroll
        for (int i = 0; i < 4; i++)
#pragma unroll
            for (int j = 0; j < 4; j++)
                acc[i][j] += a_[i] * g_[j];
    }

    // ---- blend + store (b still resident in As) ----
    float bst[4][4];
#pragma unroll
    for (int j = 0; j < 4; j++) {
        float4 v = As4[(tx * 4 + j) * (GPAD / 4) + ty];
        bst[0][j] = v.x; bst[1][j] = v.y; bst[2][j] = v.z; bst[3][j] = v.w;
    }
#pragma unroll
    for (int i = 0; i < 4; i++) {
        int r = ty * 4 + i;
        int row = row0 + r;
        if (row >= nrows) continue;
        float4 o;
        float* op = &o.x;
#pragma unroll
        for (int j = 0; j < 4; j++) {
            float gate = 1.f / (1.f + __expf(-acc[i][j]));
            float a = ast[i][j], b = bst[i][j];
            op[j] = mode ? (gate * b + (1.f - gate) * a)
                         : (gate * a + (1.f - gate) * b);
        }
        *(float4*)(out + (size_t)row * D + tx * 4) = o;
    }
}

// ---------------- fused epilogue: gate0 | gate1 | normalize tails ----------
__global__ void __launch_bounds__(256, 5)
epilogue(const float* __restrict__ g1, const float* __restrict__ g2,
         const float* __restrict__ g3,
         float* __restrict__ out, float* __restrict__ user_out,
         int nb0, int nb1)
{
    int b = blockIdx.x;
    if (b < nb0) {
        gate_body(g_eagg, g_cnt_e, g_iu, g_cnt_iu, g1, g2, out, N_ITEMS, b, 0);
    } else if (b < nb0 + nb1) {
        gate_body(g_ui, g_cnt_ui, g_aagg, g_cnt_a, g2, g3, user_out, N_USERS,
                  b - nb0, 1);
    } else {
        // normalize tails: entity rows [N_ITEMS,N_ENTITIES), user rows [N_USERS,N_USER_NODES)
        int nb = gridDim.x - nb0 - nb1;
        int gid = (b - nb0 - nb1) * 256 + threadIdx.x;
        int stride = nb * 256;
        const int nE = (N_ENTITIES - N_ITEMS) * DV4;        // 2,080,000
        const int nU = (N_USER_NODES - N_USERS) * DV4;      //   800,000
        for (int i = gid; i < nE + nU; i += stride) {
            const float* agg; const float* cnt; float* dst; int r; int c;
            if (i < nE) {
                r = N_ITEMS + (i >> 4); c = i & 15;
                agg = g_eagg; cnt = g_cnt_e; dst = out;
            } else {
                int k = i - nE;
                r = N_USERS + (k >> 4); c = k & 15;
                agg = g_aagg; cnt = g_cnt_a; dst = user_out;
            }
            float ic = 1.f / fmaxf(__ldg(cnt + r), 1.f);
            float4 v = ((const float4*)agg)[(size_t)r * DV4 + c];
            ((float4*)dst)[(size_t)r * DV4 + c] =
                make_float4(v.x * ic, v.y * ic, v.z * ic, v.w * ic);
        }
    }
}

// ---------------- launch -----------------------------------------------------
extern "C" void kernel_launch(void* const* d_in, const int* in_sizes, int n_in,
                              void* d_out, int out_size)
{
    const float* entity_emb = (const float*)d_in[0];
    const float* user_emb   = (const float*)d_in[1];
    const float* weight     = (const float*)d_in[2];
    const float* gate1_w    = (const float*)d_in[3];
    const float* gate2_w    = (const float*)d_in[4];
    const float* gate3_w    = (const float*)d_in[5];
    const int*   edge_index = (const int*)d_in[6];
    const int*   edge_type  = (const int*)d_in[7];
    const int*   uedge_index= (const int*)d_in[8];
    const int*   uedge_type = (const int*)d_in[9];
    const int*   mat_row    = (const int*)d_in[10];
    const int*   mat_col    = (const int*)d_in[11];

    int n_e  = in_sizes[7];    // 1,500,000
    int n_ue = in_sizes[9];    // 1,000,000
    int n_m  = in_sizes[10];   // 1,500,000

    float* out = (float*)d_out;
    float* user_out = out + (size_t)N_ENTITIES * D;

    cudaFuncSetAttribute(epilogue, cudaFuncAttributeMaxDynamicSharedMemorySize, GATE_SMEM);

    zero_all<<<2048, 256>>>();

    // Partition scatter blocks by L2-traffic share
    const int SG = 4736;
    double t_e = (double)n_e * 524.0;
    double t_u = (double)n_ue * 524.0;
    double t_m = (double)n_m * 1032.0;
    double tot = t_e + t_u + t_m;
    int b_e = (int)(SG * (t_e / tot) + 0.5);
    int b_u = b_e + (int)(SG * (t_u / tot) + 0.5);
    if (b_e < 1) b_e = 1;
    if (b_u <= b_e) b_u = b_e + 1;
    if (b_u >= SG) b_u = SG - 1;

    scatter_all<<<SG, 256>>>((const float4*)entity_emb, (const float4*)user_emb,
                             (const float4*)weight,
                             edge_index, edge_index + n_e, edge_type, n_e,
                             uedge_index, uedge_index + n_ue, uedge_type, n_ue,
                             mat_row, mat_col, n_m,
                             b_e, b_u);

    int nb0 = (N_ITEMS + 63) / 64;   // 782
    int nb1 = (N_USERS + 63) / 64;   // 1563
    int nbn = 1024;                  // normalize partition (grid-stride)
    epilogue<<<nb0 + nb1 + nbn, 256, GATE_SMEM>>>(gate1_w, gate2_w, gate3_w,
                                                  out, user_out, nb0, nb1);
}